// round 16
// baseline (speedup 1.0000x reference)
#include <cuda_runtime.h>

#define T_TOKENS 16384
#define HID      2048
#define NEXP     128
#define NCOL     256      // full logits [0,128) + bvh logits [128,256)
#define NCAND    32
#define TK       8

#define BM   32
#define BK   16
#define NTH  256
#define RS   20           // smem row stride in floats (80B: 16B-aligned, bank-step 20)
#define NKIT (HID / BK)   // 128 k-tiles

#define OFFV ((size_t)T_TOKENS * NEXP)
#define OFFI (OFFV + (size_t)T_TOKENS * TK)

// smem pool (floats): A tiles 2*32*20=1280, B tiles 2*256*20=10240 -> 11520 (46080 B)
// logits overlay [32][256] = 8192 floats reuses the pool after the mainloop.
#define SM_B0 1280
#define SM_BSZ 5120       // one B buffer
#define SM_ASZ 640        // one A buffer

typedef unsigned long long ull;

// ---- packed f32x2 helpers (Blackwell: 2 fp32 ops per instruction) ----
__device__ __forceinline__ ull pk2(float lo, float hi) {
    ull r;
    asm("mov.b64 %0, {%1, %2};" : "=l"(r)
        : "r"(__float_as_uint(lo)), "r"(__float_as_uint(hi)));
    return r;
}
__device__ __forceinline__ void fma2(ull& c, ull a, ull b) {
    asm("fma.rn.f32x2 %0, %1, %2, %0;" : "+l"(c) : "l"(a), "l"(b));
}
__device__ __forceinline__ ull add2(ull a, ull b) {
    ull r; asm("add.rn.f32x2 %0, %1, %2;" : "=l"(r) : "l"(a), "l"(b)); return r;
}
__device__ __forceinline__ ull sub2(ull a, ull b) {
    ull r; asm("sub.rn.f32x2 %0, %1, %2;" : "=l"(r) : "l"(a), "l"(b)); return r;
}
__device__ __forceinline__ float2 upk2(ull v) {
    unsigned lo, hi;
    asm("mov.b64 {%0, %1}, %2;" : "=r"(lo), "=r"(hi) : "l"(v));
    return make_float2(__uint_as_float(lo), __uint_as_float(hi));
}

__device__ __forceinline__ void cpa16(unsigned dst, const void* src) {
    asm volatile("cp.async.cg.shared.global [%0], [%1], 16;" :: "r"(dst), "l"(src));
}

// monotone key for float ordering
__device__ __forceinline__ unsigned monok(float x) {
    unsigned u = __float_as_uint(x);
    return (u & 0x80000000u) ? ~u : (u | 0x80000000u);
}

__device__ __forceinline__ float wmax(float v) {
#pragma unroll
    for (int o = 16; o > 0; o >>= 1) v = fmaxf(v, __shfl_xor_sync(0xffffffffu, v, o));
    return v;
}
__device__ __forceinline__ float wsum(float v) {
#pragma unroll
    for (int o = 16; o > 0; o >>= 1) v += __shfl_xor_sync(0xffffffffu, v, o);
    return v;
}
__device__ __forceinline__ ull wmaxu(ull v) {
#pragma unroll
    for (int o = 16; o > 0; o >>= 1) {
        ull t = __shfl_xor_sync(0xffffffffu, v, o);
        v = (t > v) ? t : v;
    }
    return v;
}

// -------- selection with exact lax.top_k tie semantics (lowest index) --------
// Lane l holds probs for experts l, l+32, l+64, l+96 (full p*, bvh q*).
__device__ __forceinline__ void run_select(
    int tok, int l,
    float p0, float p1, float p2, float p3,
    float q0, float q1, float q2, float q3,
    float* __restrict__ out)
{
    const unsigned FULL = 0xffffffffu;

    // stage 1: top-32 of bvh probs; tie -> lowest expert id
    ull k0 = ((ull)monok(q0) << 32) | (unsigned)(127 - l);
    ull k1 = ((ull)monok(q1) << 32) | (unsigned)(95 - l);
    ull k2 = ((ull)monok(q2) << 32) | (unsigned)(63 - l);
    ull k3 = ((ull)monok(q3) << 32) | (unsigned)(31 - l);
    int my_cand = 0;
#pragma unroll 1
    for (int c = 0; c < NCAND; ++c) {
        ull loc  = (k0 > k1) ? k0 : k1;
        ull loc2 = (k2 > k3) ? k2 : k3;
        loc = (loc > loc2) ? loc : loc2;
        ull best = wmaxu(loc);
        int id = 127 - (int)(unsigned)(best & 0xffffffffu);
        if (l == c) my_cand = id;
        if ((id & 31) == l) {
            int slot = id >> 5;
            if      (slot == 0) k0 = 0;
            else if (slot == 1) k1 = 0;
            else if (slot == 2) k2 = 0;
            else                k3 = 0;
        }
    }

    // gather full prob of my candidate
    int srcl = my_cand & 31, slot = my_cand >> 5;
    float v0 = __shfl_sync(FULL, p0, srcl);
    float v1 = __shfl_sync(FULL, p1, srcl);
    float v2 = __shfl_sync(FULL, p2, srcl);
    float v3 = __shfl_sync(FULL, p3, srcl);
    float cp = (slot == 0) ? v0 : (slot == 1) ? v1 : (slot == 2) ? v2 : v3;

    // stage 2: top-8 among 32 candidates; tie -> lowest candidate position
    ull mykey = ((ull)monok(cp) << 32) | (unsigned)(31 - l);
    float rv = 0.0f; int ri = 0;
#pragma unroll 1
    for (int r = 0; r < TK; ++r) {
        ull best = wmaxu(mykey);
        int cw = 31 - (int)(unsigned)(best & 0xffffffffu);
        float wv = __shfl_sync(FULL, cp, cw);
        int   wi = __shfl_sync(FULL, my_cand, cw);
        if (l == r)  { rv = wv; ri = wi; }
        if (l == cw) mykey = 0;
    }

    float ssum = wsum(rv);   // lanes >= 8 contribute 0
    if (l < TK) {
        out[OFFV + (size_t)tok * TK + l] = rv / ssum;
        out[OFFI + (size_t)tok * TK + l] = (float)ri;
    }
}

// ====== fused GEMM (cp.async pipeline, blocked-Kahan) + softmax + top-k ======
__global__ __launch_bounds__(NTH, 2)
void router_kernel(const float* __restrict__ X,
                   const float* __restrict__ Wo,
                   const float* __restrict__ Wb,
                   float* __restrict__ out)
{
    __shared__ float sm[SM_B0 + 2 * SM_BSZ];   // 46080 B

    const int tid = threadIdx.x;
    const int m0  = blockIdx.x * BM;

    // compute mapping: 8 tokens x 4 experts per thread.
    // experts for thread = { eg, eg+64, eg+128, eg+192 }  (bank-friendly stride-1 rows)
    const int eg = tid & 63;
    const int tg = tid >> 6;

    // ---- cp.async loader setup ----
    const bool aload = tid < 128;
    const float* wbase = (tid < NEXP) ? (Wo + (size_t)tid * HID)
                                      : (Wb + (size_t)(tid - NEXP) * HID);
    const float* abase = X + (size_t)(m0 + (tid >> 2)) * HID + (tid & 3) * 4;
    const unsigned smb = (unsigned)__cvta_generic_to_shared(sm);
    const unsigned dB  = smb + (unsigned)(SM_B0 + tid * RS) * 4u;
    const unsigned dA  = smb + (unsigned)((tid >> 2) * RS + (tid & 3) * 4) * 4u;

    auto issue = [&](int kt, int b) {
        const float* ws = wbase + kt * BK;
#pragma unroll
        for (int c = 0; c < 4; ++c)
            cpa16(dB + (unsigned)b * (SM_BSZ * 4u) + (unsigned)c * 16u, ws + c * 4);
        if (aload) cpa16(dA + (unsigned)b * (SM_ASZ * 4u), abase + kt * BK);
        asm volatile("cp.async.commit_group;" ::: "memory");
    };

    // main accumulators + Kahan compensation (nc = minus the compensation)
    ull acc[8][2], nc[8][2];
#pragma unroll
    for (int t = 0; t < 8; ++t) {
        acc[t][0] = 0ull; acc[t][1] = 0ull;
        nc[t][0]  = 0ull; nc[t][1]  = 0ull;
    }

    issue(0, 0);
    asm volatile("cp.async.wait_group 0;" ::: "memory");
    __syncthreads();

    int buf = 0;
    for (int kt = 0; kt < NKIT; ++kt) {
        if (kt + 1 < NKIT) issue(kt + 1, buf ^ 1);

        // per-tile partial accumulator (16 serial products, fp32)
        ull blk[8][2];
#pragma unroll
        for (int t = 0; t < 8; ++t) { blk[t][0] = 0ull; blk[t][1] = 0ull; }

        const float* Ab = sm + buf * SM_ASZ + tg * 8 * RS;
        const float* Bb = sm + SM_B0 + buf * SM_BSZ + eg * RS;
#pragma unroll
        for (int g = 0; g < 4; ++g) {
            float4 b0 = *(const float4*)(Bb + g * 4);
            float4 b1 = *(const float4*)(Bb + 64 * RS + g * 4);
            float4 b2 = *(const float4*)(Bb + 128 * RS + g * 4);
            float4 b3 = *(const float4*)(Bb + 192 * RS + g * 4);
            ull bp0[4] = { pk2(b0.x,b1.x), pk2(b0.y,b1.y), pk2(b0.z,b1.z), pk2(b0.w,b1.w) };
            ull bp1[4] = { pk2(b2.x,b3.x), pk2(b2.y,b3.y), pk2(b2.z,b3.z), pk2(b2.w,b3.w) };
#pragma unroll
            for (int t = 0; t < 8; ++t) {
                float4 a = *(const float4*)(Ab + t * RS + g * 4);
                ull ap;
                ap = pk2(a.x, a.x); fma2(blk[t][0], ap, bp0[0]); fma2(blk[t][1], ap, bp1[0]);
                ap = pk2(a.y, a.y); fma2(blk[t][0], ap, bp0[1]); fma2(blk[t][1], ap, bp1[1]);
                ap = pk2(a.z, a.z); fma2(blk[t][0], ap, bp0[2]); fma2(blk[t][1], ap, bp1[2]);
                ap = pk2(a.w, a.w); fma2(blk[t][0], ap, bp0[3]); fma2(blk[t][1], ap, bp1[3]);
            }
        }

        // Kahan fold: acc += blk with compensation (precision-critical; keep)
#pragma unroll
        for (int t = 0; t < 8; ++t) {
#pragma unroll
            for (int j = 0; j < 2; ++j) {
                ull y  = add2(blk[t][j], nc[t][j]);
                ull tt = add2(acc[t][j], y);
                ull d  = sub2(tt, acc[t][j]);
                nc[t][j] = sub2(y, d);
                acc[t][j] = tt;
            }
        }

        if (kt + 1 < NKIT) {
            asm volatile("cp.async.wait_group 0;" ::: "memory");
            __syncthreads();
            buf ^= 1;
        }
    }

    __syncthreads();   // all smem tile reads done before logits overlay

    // logits overlay: sm[tok_local][col], 32x256 floats
#pragma unroll
    for (int t = 0; t < 8; ++t) {
        int tl = tg * 8 + t;
        float2 c0 = upk2(add2(acc[t][0], nc[t][0]));   // experts eg, eg+64
        float2 c1 = upk2(add2(acc[t][1], nc[t][1]));   // experts eg+128, eg+192
        sm[tl * NCOL + eg      ] = c0.x;
        sm[tl * NCOL + eg + 64 ] = c0.y;
        sm[tl * NCOL + eg + 128] = c1.x;
        sm[tl * NCOL + eg + 192] = c1.y;
    }
    __syncthreads();

    // ---------------- epilogue: one warp per token, 4 tokens/warp ----------------
    const int l    = tid & 31;
    const int warp = tid >> 5;

#pragma unroll 1
    for (int i = 0; i < 4; ++i) {
        const int tl  = warp * 4 + i;
        const int tok = m0 + tl;
        const float* row = sm + tl * NCOL;

        float f0 = row[l], f1 = row[l + 32], f2 = row[l + 64], f3 = row[l + 96];
        float g0 = row[128 + l], g1 = row[160 + l], g2 = row[192 + l], g3 = row[224 + l];

        // full softmax (jax: exp(x - max) / sum)
        float mx  = wmax(fmaxf(fmaxf(f0, f1), fmaxf(f2, f3)));
        float e0 = expf(f0 - mx), e1 = expf(f1 - mx), e2 = expf(f2 - mx), e3 = expf(f3 - mx);
        float inv = 1.0f / wsum(e0 + e1 + e2 + e3);
        float p0 = e0 * inv, p1 = e1 * inv, p2 = e2 * inv, p3 = e3 * inv;
        {
            float* po = out + (size_t)tok * NEXP;
            po[l] = p0; po[l + 32] = p1; po[l + 64] = p2; po[l + 96] = p3;
        }

        // bvh softmax
        float bmx = wmax(fmaxf(fmaxf(g0, g1), fmaxf(g2, g3)));
        float q0 = expf(g0 - bmx), q1 = expf(g1 - bmx), q2 = expf(g2 - bmx), q3 = expf(g3 - bmx);
        float binv = 1.0f / wsum(q0 + q1 + q2 + q3);
        q0 *= binv; q1 *= binv; q2 *= binv; q3 *= binv;

        run_select(tok, l, p0, p1, p2, p3, q0, q1, q2, q3, out);
    }
}

extern "C" void kernel_launch(void* const* d_in, const int* in_sizes, int n_in,
                              void* d_out, int out_size) {
    (void)in_sizes; (void)n_in; (void)out_size;
    const float* X  = (const float*)d_in[0];
    const float* Wo = (const float*)d_in[1];
    const float* Wb = (const float*)d_in[2];
    router_kernel<<<T_TOKENS / BM, NTH>>>(X, Wo, Wb, (float*)d_out);
}